// round 15
// baseline (speedup 1.0000x reference)
#include <cuda_runtime.h>
#include <cuda_bf16.h>

// LengthRegulator: out[b,t,:] = x[b, searchsorted(cumsum(dur[b]), t, 'right'), :]
// (zeros for t >= total duration). Shapes fixed by the problem:
//   x: [16, 512, 512] f32, durations: [16, 512] i32, out: [16, 4096, 512] f32.
//
// R13 (FPW=1, 128-thr blocks, __stcs, PDL) pushed one step further along the
// measured shorter-warp law: HALF-row warps (1KB each: 2 LDG.128 + 2 STG.128),
// 131072 warps in 32768 x 128-thread blocks.

static constexpr int B  = 16;
static constexpr int S  = 512;
static constexpr int H  = 512;
static constexpr int T  = 4096;
static constexpr int H4 = H / 4;          // 128 float4 per row

// Scratch: per-frame source-token index (S means "invalid / zero frame").
__device__ int g_idx[B * T];

// One block per batch. Warp-shuffle inclusive scan, then scatter: token j
// writes its index over frames [cum[j-1], cum[j]); tail gets S. Signals
// dependents once this block's g_idx stores are complete.
__global__ void scan_idx_kernel(const int* __restrict__ durations) {
    __shared__ int warp_sums[16];
    __shared__ int s_total;
    const int b    = blockIdx.x;
    const int tid  = threadIdx.x;         // blockDim.x == S == 512
    const int lane = tid & 31;
    const int wid  = tid >> 5;            // 16 warps

    const int d = durations[b * S + tid];

    int v = d;
    #pragma unroll
    for (int off = 1; off < 32; off <<= 1) {
        int n = __shfl_up_sync(0xffffffffu, v, off);
        if (lane >= off) v += n;
    }
    if (lane == 31) warp_sums[wid] = v;
    __syncthreads();

    if (wid == 0 && lane < 16) {
        int w = warp_sums[lane];
        #pragma unroll
        for (int off = 1; off < 16; off <<= 1) {
            int n = __shfl_up_sync(0xffffu, w, off);
            if (lane >= off) w += n;
        }
        warp_sums[lane] = w;
        if (lane == 15) s_total = w;
    }
    __syncthreads();

    const int cum   = v + (wid > 0 ? warp_sums[wid - 1] : 0);  // inclusive
    const int start = cum - d;                                  // exclusive
    const int total = s_total;
    int* __restrict__ gi = g_idx + b * T;

    for (int t = start; t < cum; ++t) gi[t] = tid;
    for (int t = total + tid; t < T; t += S) gi[t] = S;

    __syncthreads();
    asm volatile("griddepcontrol.launch_dependents;" ::: "memory");
}

// One WARP per HALF output row: 2 independent LDG.128 + 2 streaming STG.128
// per lane. Shortest uniform warp lifetime yet (1KB moved per warp).
__global__ void __launch_bounds__(128)
gather_kernel(const float4* __restrict__ x, float4* __restrict__ out) {
    const int w    = blockIdx.x * (blockDim.x >> 5) + (threadIdx.x >> 5);
    const int row  = w >> 1;              // two warps per row
    const int half = (w & 1) << 6;        // 0 or 64 float4s
    const int lane = threadIdx.x & 31;
    const int b    = row >> 12;           // / T

    // Block until the scan grid has published g_idx.
    asm volatile("griddepcontrol.wait;" ::: "memory");

    const int idx = g_idx[row];           // warp-uniform (1 sector)
    float4* o = out + ((long long)row << 7) + half;

    if (idx < S) {
        const float4* s = x + ((long long)((b << 9) + idx) << 7) + half;
        float4 v0 = s[lane];
        float4 v1 = s[lane + 32];
        __stcs(&o[lane],      v0);
        __stcs(&o[lane + 32], v1);
    } else {
        const float4 z = make_float4(0.f, 0.f, 0.f, 0.f);
        __stcs(&o[lane],      z);
        __stcs(&o[lane + 32], z);
    }
}

extern "C" void kernel_launch(void* const* d_in, const int* in_sizes, int n_in,
                              void* d_out, int out_size) {
    const float* x   = (const float*)d_in[0];      // [B, S, H] f32
    const int*   dur = (const int*)d_in[1];        // [B, S]   i32
    float*       out = (float*)d_out;              // [B, T, H] f32
    (void)in_sizes; (void)n_in; (void)out_size;

    scan_idx_kernel<<<B, S>>>(dur);

    const int threads = 128;                          // 4 warps = 2 rows/block
    const int blocks  = (B * T * 2) / (threads / 32); // 32768

    cudaLaunchConfig_t cfg = {};
    cfg.gridDim  = dim3(blocks, 1, 1);
    cfg.blockDim = dim3(threads, 1, 1);
    cfg.dynamicSmemBytes = 0;
    cfg.stream = 0;
    cudaLaunchAttribute attr[1];
    attr[0].id = cudaLaunchAttributeProgrammaticStreamSerialization;
    attr[0].val.programmaticStreamSerializationAllowed = 1;
    cfg.attrs = attr;
    cfg.numAttrs = 1;

    cudaLaunchKernelEx(&cfg, gather_kernel, (const float4*)x, (float4*)out);
}

// round 16
// speedup vs baseline: 1.0252x; 1.0252x over previous
#include <cuda_runtime.h>
#include <cuda_bf16.h>

// LengthRegulator: out[b,t,:] = x[b, searchsorted(cumsum(dur[b]), t, 'right'), :]
// (zeros for t >= total duration). Shapes fixed by the problem:
//   x: [16, 512, 512] f32, durations: [16, 512] i32, out: [16, 4096, 512] f32.
//
// Converged optimum (R13): FPW=1 (one warp per output row — MLP=4 LDG.128,
// shortest uniform warp that still hides L2 latency), 128-thread blocks
// (1 warp/SMSP), __stcs evict-first stores (smooths DRAM writeback across
// the replay period), PDL (scan hidden under the 16384-block dispatch ramp).
// Measured: gather at the practical LTS ceiling; every structural departure
// (half-row, multi-row, token-scatter, fused, TMA bulk, 256-thr blocks)
// regressed in controlled experiments.

static constexpr int B  = 16;
static constexpr int S  = 512;
static constexpr int H  = 512;
static constexpr int T  = 4096;
static constexpr int H4 = H / 4;          // 128 float4 per row

// Scratch: per-frame source-token index (S means "invalid / zero frame").
__device__ int g_idx[B * T];

// One block per batch. Warp-shuffle inclusive scan, then scatter: token j
// writes its index over frames [cum[j-1], cum[j]); tail gets S. Signals
// dependents once this block's g_idx stores are complete.
__global__ void scan_idx_kernel(const int* __restrict__ durations) {
    __shared__ int warp_sums[16];
    __shared__ int s_total;
    const int b    = blockIdx.x;
    const int tid  = threadIdx.x;         // blockDim.x == S == 512
    const int lane = tid & 31;
    const int wid  = tid >> 5;            // 16 warps

    const int d = durations[b * S + tid];

    int v = d;
    #pragma unroll
    for (int off = 1; off < 32; off <<= 1) {
        int n = __shfl_up_sync(0xffffffffu, v, off);
        if (lane >= off) v += n;
    }
    if (lane == 31) warp_sums[wid] = v;
    __syncthreads();

    if (wid == 0 && lane < 16) {
        int w = warp_sums[lane];
        #pragma unroll
        for (int off = 1; off < 16; off <<= 1) {
            int n = __shfl_up_sync(0xffffu, w, off);
            if (lane >= off) w += n;
        }
        warp_sums[lane] = w;
        if (lane == 15) s_total = w;
    }
    __syncthreads();

    const int cum   = v + (wid > 0 ? warp_sums[wid - 1] : 0);  // inclusive
    const int start = cum - d;                                  // exclusive
    const int total = s_total;
    int* __restrict__ gi = g_idx + b * T;

    for (int t = start; t < cum; ++t) gi[t] = tid;
    for (int t = total + tid; t < T; t += S) gi[t] = S;

    __syncthreads();
    asm volatile("griddepcontrol.launch_dependents;" ::: "memory");
}

// One WARP per output row: 4 independent LDG.128 + 4 streaming STG.128 per
// lane, perfectly uniform, shortest warp lifetime that keeps MLP=4.
__global__ void __launch_bounds__(128)
gather_kernel(const float4* __restrict__ x, float4* __restrict__ out) {
    const int row  = blockIdx.x * (blockDim.x >> 5) + (threadIdx.x >> 5);
    const int lane = threadIdx.x & 31;
    const int b    = row >> 12;           // / T

    // Block until the scan grid has published g_idx.
    asm volatile("griddepcontrol.wait;" ::: "memory");

    const int idx = g_idx[row];           // warp-uniform (1 sector)
    float4* o = out + ((long long)row << 7);

    if (idx < S) {
        const float4* s = x + ((long long)((b << 9) + idx) << 7);
        float4 v0 = s[lane];
        float4 v1 = s[lane + 32];
        float4 v2 = s[lane + 64];
        float4 v3 = s[lane + 96];
        __stcs(&o[lane],      v0);
        __stcs(&o[lane + 32], v1);
        __stcs(&o[lane + 64], v2);
        __stcs(&o[lane + 96], v3);
    } else {
        const float4 z = make_float4(0.f, 0.f, 0.f, 0.f);
        __stcs(&o[lane],      z);
        __stcs(&o[lane + 32], z);
        __stcs(&o[lane + 64], z);
        __stcs(&o[lane + 96], z);
    }
}

extern "C" void kernel_launch(void* const* d_in, const int* in_sizes, int n_in,
                              void* d_out, int out_size) {
    const float* x   = (const float*)d_in[0];      // [B, S, H] f32
    const int*   dur = (const int*)d_in[1];        // [B, S]   i32
    float*       out = (float*)d_out;              // [B, T, H] f32
    (void)in_sizes; (void)n_in; (void)out_size;

    scan_idx_kernel<<<B, S>>>(dur);

    const int threads = 128;                       // 4 warps = 4 rows/block
    const int blocks  = (B * T) / (threads / 32);  // 16384

    cudaLaunchConfig_t cfg = {};
    cfg.gridDim  = dim3(blocks, 1, 1);
    cfg.blockDim = dim3(threads, 1, 1);
    cfg.dynamicSmemBytes = 0;
    cfg.stream = 0;
    cudaLaunchAttribute attr[1];
    attr[0].id = cudaLaunchAttributeProgrammaticStreamSerialization;
    attr[0].val.programmaticStreamSerializationAllowed = 1;
    cfg.attrs = attr;
    cfg.numAttrs = 1;

    cudaLaunchKernelEx(&cfg, gather_kernel, (const float4*)x, (float4*)out);
}